// round 17
// baseline (speedup 1.0000x reference)
#include <cuda_runtime.h>
#include <cuda_bf16.h>
#include <cstdint>
#include <math.h>

// ---------------- problem constants ----------------
#define N_NODES 50000
#define E_EDGES 300000
#define F_IN    128
#define HID     256
#define G_GRP   1000
#define NUM_GC  5
#define NH      (N_NODES * HID)
#define NROWBLK ((N_NODES + 7) / 8)
#define SCANBLK ((N_NODES + 255) / 256)

typedef unsigned long long ull;

// ---------------- scratch ----------------
__device__ float d_scratch[4 * (size_t)NH + 1000000];
__device__ int d_iscratch[3 * N_NODES + 1 + E_EDGES + 512];

// ---------------- helpers ----------------
__device__ __forceinline__ void ffma2(ull& d, ull a, ull b) {
    asm("fma.rn.f32x2 %0, %1, %2, %0;" : "+l"(d) : "l"(a), "l"(b));
}
__device__ __forceinline__ ull pack2(float x, float y) {
    ull r;
    asm("mov.b64 %0, {%1, %2};" : "=l"(r) : "f"(x), "f"(y));
    return r;
}
__device__ __forceinline__ void unpack2(float& lo, float& hi, ull v) {
    asm("mov.b64 {%0, %1}, %2;" : "=f"(lo), "=f"(hi) : "l"(v));
}
__device__ __forceinline__ uint32_t tf32hi_u(float x) {
    uint32_t u;
    asm("cvt.rna.tf32.f32 %0, %1;" : "=r"(u) : "f"(x));
    return u;
}
__device__ __forceinline__ float warp_sum(float v) {
#pragma unroll
    for (int o = 16; o; o >>= 1) v += __shfl_xor_sync(0xffffffffu, v, o);
    return v;
}
__device__ __forceinline__ float block_sum_256(float v, float* sh) {
    v = warp_sum(v);
    if ((threadIdx.x & 31) == 0) sh[threadIdx.x >> 5] = v;
    __syncthreads();
    if (threadIdx.x < 32) {
        float t = (threadIdx.x < 8) ? sh[threadIdx.x] : 0.f;
        t = warp_sum(t);
        if (threadIdx.x == 0) sh[8] = t;
    }
    __syncthreads();
    float r = sh[8];
    __syncthreads();
    return r;
}
__device__ __forceinline__ float sum8(float4 a, float4 b) {
    return a.x + a.y + a.z + a.w + b.x + b.y + b.z + b.w;
}
__device__ __forceinline__ float sumsq8(float4 a, float4 b) {
    return a.x*a.x + a.y*a.y + a.z*a.z + a.w*a.w
         + b.x*b.x + b.y*b.y + b.z*b.z + b.w*b.w;
}

__global__ void init_kernel(int* __restrict__ cnt, int n1,
                            float* __restrict__ pool, int n2,
                            float* __restrict__ sm, int n3)
{
    int i = blockIdx.x * blockDim.x + threadIdx.x;
    if (i < n1) cnt[i] = 0;
    if (i < n2) pool[i] = 0.f;
    if (i < n3) sm[i] = 0.f;
}

// ============ 128x128x16 tf32 tensor-core GEMM (3xTF32 split) ============
// mma.sync.m16n8k8; fragment-major smem layouts; 8 warps in 4(m)x2(n) grid,
// warp tile 32x64. Dynamic smem 64KB: [A0 4096][A1 4096][B0 4096][B1 4096] fl.
__device__ __forceinline__ void mma_tf32(float* c, uint4 a, uint2 b) {
    asm volatile(
        "mma.sync.aligned.m16n8k8.row.col.f32.tf32.tf32.f32 "
        "{%0,%1,%2,%3}, {%4,%5,%6,%7}, {%8,%9}, {%0,%1,%2,%3};"
        : "+f"(c[0]), "+f"(c[1]), "+f"(c[2]), "+f"(c[3])
        : "r"(a.x), "r"(a.y), "r"(a.z), "r"(a.w), "r"(b.x), "r"(b.y));
}

#define TM_SMEM_BYTES 65536

// load one k16 chunk into buffer `buf` with hi/lo split, fragment-major layout
__device__ __forceinline__ void tm_load_chunk(
    const float* __restrict__ A, const float* __restrict__ B,
    float* __restrict__ sA, float* __restrict__ sB,
    int M, int Nn, int K, int row0, int col0, int kc, int tid)
{
#pragma unroll
    for (int p = 0; p < 2; p++) {
        int q = tid + p * 256;
        // ---- A: 128 rows x 16 k ----
        {
            int row = q >> 2, kk0 = (q & 3) * 4;
            float4 v = make_float4(0.f, 0.f, 0.f, 0.f);
            if (row0 + row < M)
                v = *reinterpret_cast<const float4*>(&A[(size_t)(row0 + row) * K + kc + kk0]);
            float vals[4] = {v.x, v.y, v.z, v.w};
            int mt = row >> 4, r = row & 15;
            int rbit = (r >> 3);            // 0/1
            int g4 = (r & 7) * 4;
#pragma unroll
            for (int j = 0; j < 4; j++) {
                int kloc = kk0 + j;
                int k8 = kloc >> 3, kk = kloc & 7;
                int reg = rbit + ((kk >> 2) << 1);
                int off = ((k8 * 8 + mt) * 2) * 128 + g4 + (kk & 3) * 4 + reg;
                // NOTE: lane*4 => (g*4 + (kk&3))*4? No: lane = g4/4*4... see below
                // lane = (r&7)*4 + (kk&3); offset = lane*4 + reg
                off = ((k8 * 8 + mt) * 2) * 128 + ((r & 7) * 4 + (kk & 3)) * 4 + reg;
                uint32_t hi = tf32hi_u(vals[j]);
                float hif = __uint_as_float(hi);
                uint32_t lo = tf32hi_u(vals[j] - hif);
                sA[off] = hif;
                sA[off + 128] = __uint_as_float(lo);
            }
        }
        // ---- B: 16 k x 128 cols ----
        {
            int krow = q >> 5, n0 = (q & 31) * 4;
            float4 w = *reinterpret_cast<const float4*>(
                &B[(size_t)(kc + krow) * Nn + col0 + n0]);
            float vals[4] = {w.x, w.y, w.z, w.w};
            int k8 = krow >> 3, t = krow & 3;
            int reg = (krow & 7) >> 2;
#pragma unroll
            for (int j = 0; j < 4; j++) {
                int n = n0 + j;
                int nt = n >> 3, g = n & 7;
                int off = ((k8 * 16 + nt) * 2) * 64 + (g * 4 + t) * 2 + reg;
                uint32_t hi = tf32hi_u(vals[j]);
                float hif = __uint_as_float(hi);
                uint32_t lo = tf32hi_u(vals[j] - hif);
                sB[off] = hif;
                sB[off + 64] = __uint_as_float(lo);
            }
        }
    }
}

__device__ __forceinline__ void sgemm_body(
    const float* __restrict__ A, const float* __restrict__ B,
    const float* __restrict__ bias, float* __restrict__ C,
    int M, int Nn, int K)
{
    extern __shared__ float smem[];
    float* sA = smem;            // 2 x 4096
    float* sB = smem + 8192;     // 2 x 4096

    const int tid = threadIdx.x;
    const int warp = tid >> 5, lane = tid & 31;
    const int wm = warp & 3, wn = warp >> 2;
    const int row0 = blockIdx.y * 128;
    const int col0 = blockIdx.x * 128;
    const int KT = K >> 4;

    float c[2][8][4];
#pragma unroll
    for (int i = 0; i < 2; i++)
#pragma unroll
        for (int j = 0; j < 8; j++)
#pragma unroll
            for (int q = 0; q < 4; q++) c[i][j][q] = 0.f;

    tm_load_chunk(A, B, sA, sB, M, Nn, K, row0, col0, 0, tid);
    __syncthreads();

    for (int kt = 0; kt < KT; kt++) {
        const int buf = kt & 1;
        if (kt + 1 < KT) {
            const int nb = buf ^ 1;
            tm_load_chunk(A, B, sA + nb * 4096, sB + nb * 4096,
                          M, Nn, K, row0, col0, (kt + 1) << 4, tid);
        }
        const float* bA = sA + buf * 4096;
        const float* bB = sB + buf * 4096;

#pragma unroll
        for (int k8 = 0; k8 < 2; k8++) {
            uint4 ahi[2], alo[2];
#pragma unroll
            for (int i = 0; i < 2; i++) {
                int mt = wm * 2 + i;
                int off = ((k8 * 8 + mt) * 2) * 128 + lane * 4;
                ahi[i] = *reinterpret_cast<const uint4*>(&bA[off]);
                alo[i] = *reinterpret_cast<const uint4*>(&bA[off + 128]);
            }
#pragma unroll
            for (int j = 0; j < 8; j++) {
                int nt = wn * 8 + j;
                int boff = ((k8 * 16 + nt) * 2) * 64 + lane * 2;
                uint2 bhi = *reinterpret_cast<const uint2*>(&bB[boff]);
                uint2 blo = *reinterpret_cast<const uint2*>(&bB[boff + 64]);
#pragma unroll
                for (int i = 0; i < 2; i++) {
                    mma_tf32(c[i][j], ahi[i], bhi);
                    mma_tf32(c[i][j], ahi[i], blo);
                    mma_tf32(c[i][j], alo[i], bhi);
                }
            }
        }
        __syncthreads();
    }

    // epilogue: c0,c1 -> (r, 2t),(r,2t+1); c2,c3 -> (r+8, .)
    const int g = lane >> 2, t2 = (lane & 3) * 2;
#pragma unroll
    for (int i = 0; i < 2; i++) {
        int rA = row0 + wm * 32 + i * 16 + g;
#pragma unroll
        for (int j = 0; j < 8; j++) {
            int col = col0 + wn * 64 + j * 8 + t2;
            float b0 = 0.f, b1 = 0.f;
            if (bias) { b0 = bias[col]; b1 = bias[col + 1]; }
            if (rA < M) {
                float2 o = make_float2(c[i][j][0] + b0, c[i][j][1] + b1);
                *reinterpret_cast<float2*>(&C[(size_t)rA * Nn + col]) = o;
            }
            if (rA + 8 < M) {
                float2 o = make_float2(c[i][j][2] + b0, c[i][j][3] + b1);
                *reinterpret_cast<float2*>(&C[(size_t)(rA + 8) * Nn + col]) = o;
            }
        }
    }
}

__global__ void __launch_bounds__(256, 2) sgemm128(
    const float* __restrict__ A, const float* __restrict__ B,
    const float* __restrict__ bias, float* __restrict__ C,
    int M, int Nn, int K)
{
    sgemm_body(A, B, bias, C, M, Nn, K);
}

__global__ void __launch_bounds__(256, 2) sgemm128_b2(
    const float* __restrict__ A,
    const float* __restrict__ B0, const float* __restrict__ B1,
    const float* __restrict__ bias0, const float* __restrict__ bias1,
    float* __restrict__ C0, float* __restrict__ C1,
    int M, int Nn, int K)
{
    if (blockIdx.z == 0) sgemm_body(A, B0, bias0, C0, M, Nn, K);
    else                 sgemm_body(A, B1, bias1, C1, M, Nn, K);
}

__global__ void __launch_bounds__(256, 2) sgemm128_g2(
    const float* __restrict__ A0, const float* __restrict__ B0,
    const float* __restrict__ bias0, float* __restrict__ C0,
    const float* __restrict__ A1, const float* __restrict__ B1,
    const float* __restrict__ bias1, float* __restrict__ C1,
    int M, int Nn, int K)
{
    if (blockIdx.z == 0) sgemm_body(A0, B0, bias0, C0, M, Nn, K);
    else                 sgemm_body(A1, B1, bias1, C1, M, Nn, K);
}

// ------ atb body: C[256,256] += A[L,256]^T @ B[L,256] (split-K atomics) ----
__device__ __forceinline__ void atb_body(
    const float* __restrict__ A, const float* __restrict__ B,
    float* __restrict__ C, int L, int lstart, int lend)
{
    __shared__ __align__(16) float As[32][128];
    __shared__ __align__(16) float Bs[32][64];

    const int tid = threadIdx.x;
    const int tx = tid & 15;
    const int ty = tid >> 4;
    const int ar0 = blockIdx.y * 64;
    const int bc0 = blockIdx.x * 64;

    ull acc[4][2];
#pragma unroll
    for (int i = 0; i < 4; i++) { acc[i][0] = 0ull; acc[i][1] = 0ull; }

    for (int l0 = lstart; l0 < lend; l0 += 32) {
#pragma unroll
        for (int p = 0; p < 2; p++) {
            int id = tid + p * 256;
            int lr = id >> 4;
            int c4 = (id & 15) * 4;
            int l = l0 + lr;
            float4 avv, bvv;
            if (l < lend) {
                avv = *reinterpret_cast<const float4*>(&A[(size_t)l * HID + ar0 + c4]);
                bvv = *reinterpret_cast<const float4*>(&B[(size_t)l * HID + bc0 + c4]);
            } else { avv = make_float4(0,0,0,0); bvv = avv; }
            float am[4] = {avv.x, avv.y, avv.z, avv.w};
#pragma unroll
            for (int m = 0; m < 4; m++)
                *reinterpret_cast<ull*>(&As[lr][2 * (c4 + m)]) = pack2(am[m], am[m]);
            *reinterpret_cast<float4*>(&Bs[lr][c4]) = bvv;
        }
        __syncthreads();

#pragma unroll
        for (int l = 0; l < 32; l++) {
            ulonglong2 a01 = *reinterpret_cast<const ulonglong2*>(&As[l][ty * 8]);
            ulonglong2 a23 = *reinterpret_cast<const ulonglong2*>(&As[l][ty * 8 + 4]);
            ulonglong2 bp  = *reinterpret_cast<const ulonglong2*>(&Bs[l][tx * 4]);
            ull ap[4] = {a01.x, a01.y, a23.x, a23.y};
#pragma unroll
            for (int i = 0; i < 4; i++) {
                ffma2(acc[i][0], ap[i], bp.x);
                ffma2(acc[i][1], ap[i], bp.y);
            }
        }
        __syncthreads();
    }

#pragma unroll
    for (int i = 0; i < 4; i++) {
        float c0, c1, c2, c3;
        unpack2(c0, c1, acc[i][0]); unpack2(c2, c3, acc[i][1]);
        float* base = &C[(size_t)(ar0 + ty * 4 + i) * HID + bc0 + tx * 4];
        atomicAdd(base + 0, c0); atomicAdd(base + 1, c1);
        atomicAdd(base + 2, c2); atomicAdd(base + 3, c3);
    }
}

__global__ void __launch_bounds__(256) atb_sym_kernel(
    const float* __restrict__ A, float* __restrict__ C, int L, int rows_per_z)
{
    if (blockIdx.y > blockIdx.x) return;
    int lstart = blockIdx.z * rows_per_z;
    int lend = min(L, lstart + rows_per_z);
    atb_body(A, A, C, L, lstart, lend);
}

__global__ void __launch_bounds__(256) atb3_kernel(
    const float* __restrict__ S,
    const float* __restrict__ Wv, const float* __restrict__ Wk, const float* __restrict__ Wq,
    float* __restrict__ U, float* __restrict__ Pk, float* __restrict__ Pq)
{
    const float* B = (blockIdx.z == 0) ? Wv : (blockIdx.z == 1) ? Wk : Wq;
    float* C = (blockIdx.z == 0) ? U : (blockIdx.z == 1) ? Pk : Pq;
    atb_body(S, B, C, HID, 0, HID);
}

__global__ void __launch_bounds__(256) atb1_kernel(
    const float* __restrict__ A, const float* __restrict__ B, float* __restrict__ C)
{
    atb_body(A, B, C, HID, 0, HID);
}

// merged: symfill (blocks 0..255) + matvec3 (blocks 256..258)
__global__ void __launch_bounds__(256) smalls1_kernel(
    float* __restrict__ S,
    const float* __restrict__ Wk, const float* __restrict__ Wv,
    const float* __restrict__ Wq, const float* __restrict__ hs,
    float* __restrict__ kk, float* __restrict__ wvhs, float* __restrict__ kq)
{
    int b = blockIdx.x, j = threadIdx.x;
    if (b < 256) {
        if ((b >> 6) > (j >> 6))
            S[(size_t)b * HID + j] = S[(size_t)j * HID + b];
    } else {
        int w = b - 256;
        const float* W = (w == 0) ? Wk : (w == 1) ? Wv : Wq;
        float* o = (w == 0) ? kk : (w == 1) ? wvhs : kq;
        float a = 0.f;
        for (int l = 0; l < HID; l++) a = fmaf(W[(size_t)l * HID + j], hs[l], a);
        o[j] = a;
    }
}

__global__ void __launch_bounds__(256) ln_relu_w(
    const float4* __restrict__ t, const float4* __restrict__ g,
    const float4* __restrict__ b, float4* __restrict__ out)
{
    int row = blockIdx.x * 8 + (threadIdx.x >> 5);
    if (row >= N_NODES) return;
    int lane = threadIdx.x & 31;
    const float4* tr = t + (size_t)row * 64;
    float4 v0 = tr[lane], v1 = tr[lane + 32];
    float s  = warp_sum(sum8(v0, v1));
    float s2 = warp_sum(sumsq8(v0, v1));
    float mean = s * (1.f / HID);
    float var  = s2 * (1.f / HID) - mean * mean;
    float r = rsqrtf(var + 1e-5f);
    float4 g0 = g[lane], g1 = g[lane + 32], b0 = b[lane], b1 = b[lane + 32];
    float4 o0, o1;
    o0.x = fmaxf((v0.x - mean) * r * g0.x + b0.x, 0.f);
    o0.y = fmaxf((v0.y - mean) * r * g0.y + b0.y, 0.f);
    o0.z = fmaxf((v0.z - mean) * r * g0.z + b0.z, 0.f);
    o0.w = fmaxf((v0.w - mean) * r * g0.w + b0.w, 0.f);
    o1.x = fmaxf((v1.x - mean) * r * g1.x + b1.x, 0.f);
    o1.y = fmaxf((v1.y - mean) * r * g1.y + b1.y, 0.f);
    o1.z = fmaxf((v1.z - mean) * r * g1.z + b1.z, 0.f);
    o1.w = fmaxf((v1.w - mean) * r * g1.w + b1.w, 0.f);
    float4* orow = out + (size_t)row * 64;
    orow[lane] = o0; orow[lane + 32] = o1;
}

__global__ void __launch_bounds__(256) colsum_kernel(
    const float* __restrict__ k, float* __restrict__ colsum)
{
    int c = threadIdx.x;
    float acc = 0.f;
    for (int r = blockIdx.x; r < N_NODES; r += gridDim.x)
        acc += k[(size_t)r * HID + c];
    atomicAdd(&colsum[c], acc);
}

__global__ void __launch_bounds__(256) trace2_kernel(
    const float* __restrict__ Pk, const float* __restrict__ Wk,
    const float* __restrict__ bk, const float* __restrict__ kk,
    const float* __restrict__ Pq, const float* __restrict__ Wq,
    const float* __restrict__ bq, const float* __restrict__ kq,
    float* __restrict__ scal)
{
    __shared__ float sh[16];
    const float* P = blockIdx.x ? Pq : Pk;
    const float* W = blockIdx.x ? Wq : Wk;
    const float* b = blockIdx.x ? bq : bk;
    const float* wv = blockIdx.x ? kq : kk;
    float s = 0.f;
    for (int i = threadIdx.x; i < HID * HID; i += 256) s = fmaf(P[i], W[i], s);
    float bc_ = b[threadIdx.x];
    s += 2.f * bc_ * wv[threadIdx.x] + (float)N_NODES * bc_ * bc_;
    float tot = block_sum_256(s, sh);
    if (threadIdx.x == 0) scal[blockIdx.x ? 0 : 1] = tot;
}

__global__ void kvs_final_kernel(const float* __restrict__ kvs0,
                                 const float* __restrict__ kk, const float* __restrict__ wvhs,
                                 const float* __restrict__ bk, const float* __restrict__ bv,
                                 const float* __restrict__ scal,
                                 float* __restrict__ kvsF, float* __restrict__ kssum)
{
    int i = blockIdx.x, j = threadIdx.x;
    float sk = rsqrtf(scal[1]);
    float bki = bk[i];
    float val = kvs0[(size_t)i * HID + j] + kk[i] * bv[j] + bki * wvhs[j]
              + (float)N_NODES * bki * bv[j];
    kvsF[(size_t)i * HID + j] = val * sk;
    if (j == 0) kssum[i] = (kk[i] + (float)N_NODES * bki) * sk;
}

__global__ void __launch_bounds__(256) qprep_kernel(
    const float* __restrict__ Wq, const float* __restrict__ kvsF,
    const float* __restrict__ kssum, const float* __restrict__ bq,
    float* __restrict__ wqp, float* __restrict__ bqp, float* __restrict__ w1)
{
    int b = blockIdx.x, j = threadIdx.x;
    if (b < 256) {
        __shared__ float Ar[256];
        Ar[j] = Wq[(size_t)b * HID + j];
        __syncthreads();
        float acc = 0.f;
        for (int l = 0; l < HID; l++) acc = fmaf(Ar[l], kvsF[(size_t)l * HID + j], acc);
        wqp[(size_t)b * HID + j] = acc;
    } else if (b == 256) {
        __shared__ float bs[256];
        bs[j] = bq[j];
        __syncthreads();
        float a = 0.f;
        for (int l = 0; l < HID; l++) a = fmaf(kvsF[(size_t)l * HID + j], bs[l], a);
        bqp[j] = a;
    } else {
        int row = (b - 257) * 8 + (j >> 5);
        int lane = j & 31;
        const float4* wr = reinterpret_cast<const float4*>(&Wq[(size_t)row * HID]);
        const float4* ks = reinterpret_cast<const float4*>(kssum);
        float4 a0 = wr[lane], a1 = wr[lane + 32];
        float4 k0 = __ldg(&ks[lane]), k1 = __ldg(&ks[lane + 32]);
        float d = a0.x*k0.x + a0.y*k0.y + a0.z*k0.z + a0.w*k0.w
                + a1.x*k1.x + a1.y*k1.y + a1.z*k1.z + a1.w*k1.w;
        d = warp_sum(d);
        if (lane == 0) w1[row] = d;
    }
}

__global__ void __launch_bounds__(256) combine_kernel(
    const float* __restrict__ wqp, const float* __restrict__ Wv,
    const float* __restrict__ bqp, const float* __restrict__ bv,
    const float* __restrict__ bq, const float* __restrict__ kssum,
    float* __restrict__ scal, float* __restrict__ Wc, float* __restrict__ bc)
{
    __shared__ float sh[16];
    float rq = rsqrtf(scal[0]);
    int b = blockIdx.x, j = threadIdx.x;
    if (b < 256) {
        size_t o = (size_t)b * HID + j;
        Wc[o] = rq * wqp[o] + (float)N_NODES * Wv[o];
    } else {
        bc[j] = rq * bqp[j] + (float)N_NODES * bv[j];
        float s = block_sum_256(bq[j] * kssum[j], sh);
        if (j == 0) scal[2] = s;
    }
}

__global__ void __launch_bounds__(256) trans_epi_w(
    const float4* __restrict__ t3, const float4* __restrict__ h,
    const float4* __restrict__ w1, const float* __restrict__ scal,
    const float4* __restrict__ g1, const float4* __restrict__ b1,
    float4* __restrict__ out_xt)
{
    int row = blockIdx.x * 8 + (threadIdx.x >> 5);
    if (row >= N_NODES) return;
    int lane = threadIdx.x & 31;
    size_t ro = (size_t)row * 64;
    float4 h0 = h[ro + lane], h1v = h[ro + lane + 32];
    float4 wa = w1[lane], wb = w1[lane + 32];
    float dotl = h0.x*wa.x + h0.y*wa.y + h0.z*wa.z + h0.w*wa.w
               + h1v.x*wb.x + h1v.y*wb.y + h1v.z*wb.z + h1v.w*wb.w;
    float dot = warp_sum(dotl);
    float rq = rsqrtf(scal[0]);
    float denom = rq * (dot + scal[2]) + (float)N_NODES;
    float hi = 0.5f / denom;
    float4 t0 = t3[ro + lane], t1 = t3[ro + lane + 32];
    float4 a0, a1;
    a0.x = t0.x * hi + 0.5f * h0.x;  a0.y = t0.y * hi + 0.5f * h0.y;
    a0.z = t0.z * hi + 0.5f * h0.z;  a0.w = t0.w * hi + 0.5f * h0.w;
    a1.x = t1.x * hi + 0.5f * h1v.x; a1.y = t1.y * hi + 0.5f * h1v.y;
    a1.z = t1.z * hi + 0.5f * h1v.z; a1.w = t1.w * hi + 0.5f * h1v.w;
    float s  = warp_sum(sum8(a0, a1));
    float s2 = warp_sum(sumsq8(a0, a1));
    float mean = s * (1.f / HID);
    float var  = s2 * (1.f / HID) - mean * mean;
    float r = rsqrtf(var + 1e-5f);
    float4 gg0 = g1[lane], gg1 = g1[lane + 32], bb0 = b1[lane], bb1 = b1[lane + 32];
    float4 y0, y1;
    y0.x = fmaxf((a0.x - mean) * r * gg0.x + bb0.x, 0.f);
    y0.y = fmaxf((a0.y - mean) * r * gg0.y + bb0.y, 0.f);
    y0.z = fmaxf((a0.z - mean) * r * gg0.z + bb0.z, 0.f);
    y0.w = fmaxf((a0.w - mean) * r * gg0.w + bb0.w, 0.f);
    y1.x = fmaxf((a1.x - mean) * r * gg1.x + bb1.x, 0.f);
    y1.y = fmaxf((a1.y - mean) * r * gg1.y + bb1.y, 0.f);
    y1.z = fmaxf((a1.z - mean) * r * gg1.z + bb1.z, 0.f);
    y1.w = fmaxf((a1.w - mean) * r * gg1.w + bb1.w, 0.f);
    float ssn = warp_sum(sumsq8(y0, y1));
    float inv_n = 1.f / fmaxf(sqrtf(ssn), 1e-12f);
    y0.x *= inv_n; y0.y *= inv_n; y0.z *= inv_n; y0.w *= inv_n;
    y1.x *= inv_n; y1.y *= inv_n; y1.z *= inv_n; y1.w *= inv_n;
    out_xt[ro + lane] = y0; out_xt[ro + lane + 32] = y1;
}

__global__ void bn_coef_kernel(const float* __restrict__ gcn_b0, const float* __restrict__ gcn_b,
                               const float* __restrict__ bn_g, const float* __restrict__ bn_b,
                               const float* __restrict__ bn_mean, const float* __restrict__ bn_var,
                               float* __restrict__ coef_s, float* __restrict__ coef_t)
{
    int idx = blockIdx.x * blockDim.x + threadIdx.x;
    if (idx >= NUM_GC * HID) return;
    int layer = idx >> 8, c = idx & 255;
    float b = (layer == 0) ? gcn_b0[c] : gcn_b[(size_t)(layer - 1) * HID + c];
    float rs = rsqrtf(bn_var[idx] + 1e-5f);
    float sv = bn_g[idx] * rs;
    coef_s[idx] = sv;
    coef_t[idx] = (b - bn_mean[idx]) * sv + bn_b[idx];
}

// ---------------- CSR build ----------------
__global__ void count_kernel(const int* __restrict__ dst, int* __restrict__ cnt) {
    int e = blockIdx.x * blockDim.x + threadIdx.x;
    if (e < E_EDGES) atomicAdd(&cnt[dst[e]], 1);
}

__global__ void __launch_bounds__(256) scan_partial_kernel(
    const int* __restrict__ cnt, int* __restrict__ partial)
{
    __shared__ int sh[8];
    int i = blockIdx.x * 256 + threadIdx.x;
    int v = (i < N_NODES) ? cnt[i] : 0;
#pragma unroll
    for (int o = 16; o; o >>= 1) v += __shfl_xor_sync(0xffffffffu, v, o);
    if ((threadIdx.x & 31) == 0) sh[threadIdx.x >> 5] = v;
    __syncthreads();
    if (threadIdx.x < 8) {
        int t = sh[threadIdx.x];
#pragma unroll
        for (int o = 4; o; o >>= 1) t += __shfl_xor_sync(0xffu, t, o);
        if (threadIdx.x == 0) partial[blockIdx.x] = t;
    }
}

__global__ void __launch_bounds__(256) scan_base_kernel(
    const int* __restrict__ partial, int* __restrict__ pbase)
{
    __shared__ int sh[256];
    int t = threadIdx.x;
    int v = (t < SCANBLK) ? partial[t] : 0;
    sh[t] = v;
    __syncthreads();
#pragma unroll
    for (int d = 1; d < 256; d <<= 1) {
        int u = (t >= d) ? sh[t - d] : 0;
        __syncthreads();
        sh[t] += u;
        __syncthreads();
    }
    pbase[t] = sh[t] - v;
}

__global__ void __launch_bounds__(256) scan_fill_kernel(
    const int* __restrict__ cnt, const int* __restrict__ pbase,
    int* __restrict__ off, int* __restrict__ cur, float* __restrict__ dinv)
{
    __shared__ int wsum[8];
    int i = blockIdx.x * 256 + threadIdx.x;
    int lane = threadIdx.x & 31, wid = threadIdx.x >> 5;
    int c = (i < N_NODES) ? cnt[i] : 0;
    int v = c;
#pragma unroll
    for (int o = 1; o < 32; o <<= 1) {
        int u = __shfl_up_sync(0xffffffffu, v, o);
        if (lane >= o) v += u;
    }
    if (lane == 31) wsum[wid] = v;
    __syncthreads();
    if (threadIdx.x < 8) {
        int w = wsum[threadIdx.x];
#pragma unroll
        for (int o = 1; o < 8; o <<= 1) {
            int u = __shfl_up_sync(0xffu, w, o);
            if (threadIdx.x >= o) w += u;
        }
        wsum[threadIdx.x] = w;
    }
    __syncthreads();
    int wpre = (wid == 0) ? 0 : wsum[wid - 1];
    int excl = v - c + wpre + pbase[blockIdx.x];
    if (i < N_NODES) {
        off[i] = excl;
        cur[i] = excl;
        dinv[i] = rsqrtf((float)(c + 1));
    }
    if (i == N_NODES - 1) off[N_NODES] = E_EDGES;
}

__global__ void fill_kernel(const int* __restrict__ src, const int* __restrict__ dst,
                            const float* __restrict__ dinv,
                            int* __restrict__ cur, int* __restrict__ csrc,
                            float* __restrict__ cw)
{
    int e = blockIdx.x * blockDim.x + threadIdx.x;
    if (e >= E_EDGES) return;
    int d = dst[e];
    int s = src[e];
    int pos = atomicAdd(&cur[d], 1);
    csrc[pos] = s;
    cw[pos] = dinv[s];
}

// ------- CSR aggregation core --------
__device__ __forceinline__ float4 csr_agg_row(
    const float4* __restrict__ gw, const int* __restrict__ off,
    const int* __restrict__ csrc, const float* __restrict__ cw,
    float di, int row, int c4)
{
    float4 g = gw[(size_t)row * 64 + c4];
    float4 acc = make_float4(g.x * di, g.y * di, g.z * di, g.w * di);
    int e0 = off[row], e1 = off[row + 1];
    int j = e0;
    for (; j + 4 <= e1; j += 4) {
        int s0 = __ldg(&csrc[j]),     s1 = __ldg(&csrc[j + 1]);
        int s2 = __ldg(&csrc[j + 2]), s3 = __ldg(&csrc[j + 3]);
        float w0 = __ldg(&cw[j]),     w1 = __ldg(&cw[j + 1]);
        float w2 = __ldg(&cw[j + 2]), w3 = __ldg(&cw[j + 3]);
        float4 g0 = gw[(size_t)s0 * 64 + c4];
        float4 g1 = gw[(size_t)s1 * 64 + c4];
        float4 g2 = gw[(size_t)s2 * 64 + c4];
        float4 g3 = gw[(size_t)s3 * 64 + c4];
        acc.x = fmaf(w0, g0.x, fmaf(w1, g1.x, fmaf(w2, g2.x, fmaf(w3, g3.x, acc.x))));
        acc.y = fmaf(w0, g0.y, fmaf(w1, g1.y, fmaf(w2, g2.y, fmaf(w3, g3.y, acc.y))));
        acc.z = fmaf(w0, g0.z, fmaf(w1, g1.z, fmaf(w2, g2.z, fmaf(w3, g3.z, acc.z))));
        acc.w = fmaf(w0, g0.w, fmaf(w1, g1.w, fmaf(w2, g2.w, fmaf(w3, g3.w, acc.w))));
    }
    for (; j < e1; j++) {
        int s = __ldg(&csrc[j]);
        float w = __ldg(&cw[j]);
        float4 gv = gw[(size_t)s * 64 + c4];
        acc.x = fmaf(w, gv.x, acc.x);
        acc.y = fmaf(w, gv.y, acc.y);
        acc.z = fmaf(w, gv.z, acc.z);
        acc.w = fmaf(w, gv.w, acc.w);
    }
    acc.x *= di; acc.y *= di; acc.z *= di; acc.w *= di;
    return acc;
}

__global__ void __launch_bounds__(256) csr_agg_kernel(
    const float4* __restrict__ gw, const int* __restrict__ off,
    const int* __restrict__ csrc, const float* __restrict__ cw,
    const float* __restrict__ dinv,
    const float* __restrict__ aff_s, const float* __restrict__ aff_t,
    float4* __restrict__ outy)
{
    int row = blockIdx.x * 4 + (threadIdx.x >> 6);
    int c4 = threadIdx.x & 63;
    float di = dinv[row];
    float4 acc = csr_agg_row(gw, off, csrc, cw, di, row, c4);
    float4 s4 = *reinterpret_cast<const float4*>(&aff_s[c4 * 4]);
    float4 t4 = *reinterpret_cast<const float4*>(&aff_t[c4 * 4]);
    acc.x = fmaxf(fmaf(acc.x, s4.x, t4.x), 0.f);
    acc.y = fmaxf(fmaf(acc.y, s4.y, t4.y), 0.f);
    acc.z = fmaxf(fmaf(acc.z, s4.z, t4.z), 0.f);
    acc.w = fmaxf(fmaf(acc.w, s4.w, t4.w), 0.f);
    outy[(size_t)row * 64 + c4] = acc;
}

__global__ void __launch_bounds__(256) csr_agg_final(
    const float4* __restrict__ gw, const int* __restrict__ off,
    const int* __restrict__ csrc, const float* __restrict__ cw,
    const float* __restrict__ dinv,
    const float* __restrict__ aff_s, const float* __restrict__ aff_t,
    const int* __restrict__ batch,
    float4* __restrict__ out_g, float* __restrict__ out_pool)
{
    __shared__ float part[8];
    int sub = threadIdx.x >> 6;
    int row = blockIdx.x * 4 + sub;
    int c4 = threadIdx.x & 63;
    float di = dinv[row];
    float4 acc = csr_agg_row(gw, off, csrc, cw, di, row, c4);
    float4 s4 = *reinterpret_cast<const float4*>(&aff_s[c4 * 4]);
    float4 t4 = *reinterpret_cast<const float4*>(&aff_t[c4 * 4]);
    acc.x = fmaf(acc.x, s4.x, t4.x);
    acc.y = fmaf(acc.y, s4.y, t4.y);
    acc.z = fmaf(acc.z, s4.z, t4.z);
    acc.w = fmaf(acc.w, s4.w, t4.w);
    float ss = acc.x*acc.x + acc.y*acc.y + acc.z*acc.z + acc.w*acc.w;
    ss = warp_sum(ss);
    if ((threadIdx.x & 31) == 0) part[threadIdx.x >> 5] = ss;
    __syncthreads();
    float tot = part[sub * 2] + part[sub * 2 + 1];
    float inv_n = 1.f / fmaxf(sqrtf(tot), 1e-12f);
    acc.x *= inv_n; acc.y *= inv_n; acc.z *= inv_n; acc.w *= inv_n;
    out_g[(size_t)row * 64 + c4] = acc;
    int grp = __ldg(&batch[row]);
    float* p = &out_pool[(size_t)grp * HID + c4 * 4];
    asm volatile("red.global.add.v4.f32 [%0], {%1, %2, %3, %4};"
                 :: "l"(p), "f"(acc.x), "f"(acc.y), "f"(acc.z), "f"(acc.w) : "memory");
}

// ---------------- launcher ----------------
extern "C" void kernel_launch(void* const* d_in, const int* in_sizes, int n_in,
                              void* d_out, int out_size)
{
    const float* x       = (const float*)d_in[0];
    const int*   edge    = (const int*)  d_in[1];
    const int*   batch   = (const int*)  d_in[2];
    // d_in[3] = beta (unused)
    const float* fc_W    = (const float*)d_in[4];
    const float* fc_b    = (const float*)d_in[5];
    const float* ln0_g   = (const float*)d_in[6];
    const float* ln0_b   = (const float*)d_in[7];
    const float* Wq      = (const float*)d_in[8];
    const float* bq      = (const float*)d_in[9];
    const float* Wk      = (const float*)d_in[10];
    const float* bk      = (const float*)d_in[11];
    const float* Wv      = (const float*)d_in[12];
    const float* bv      = (const float*)d_in[13];
    const float* ln1_g   = (const float*)d_in[14];
    const float* ln1_b   = (const float*)d_in[15];
    const float* gcn_W0  = (const float*)d_in[16];
    const float* gcn_b0  = (const float*)d_in[17];
    const float* gcn_W   = (const float*)d_in[18];
    const float* gcn_b   = (const float*)d_in[19];
    const float* bn_g    = (const float*)d_in[20];
    const float* bn_b    = (const float*)d_in[21];
    const float* bn_mean = (const float*)d_in[22];
    const float* bn_var  = (const float*)d_in[23];

    const int* src = edge;
    const int* dst = edge + E_EDGES;

    float* out      = (float*)d_out;
    float* out_pool = out;
    float* out_g    = out + (size_t)G_GRP * HID;
    float* out_xt   = out_g + (size_t)N_NODES * HID;

    float* fbase = nullptr;
    int* ibase = nullptr;
    cudaGetSymbolAddress((void**)&fbase, d_scratch);
    cudaGetSymbolAddress((void**)&ibase, d_iscratch);

    float* p_h   = fbase;
    float* p_t   = fbase + (size_t)1 * NH;
    float* p_gw  = fbase + (size_t)2 * NH;
    float* p_y   = fbase + (size_t)3 * NH;

    float* p_sm   = fbase + (size_t)4 * NH;
    float* p_S    = p_sm;
    float* p_U    = p_S + HID * HID;
    float* p_Pk   = p_U + HID * HID;
    float* p_Pq   = p_Pk + HID * HID;
    float* p_kvs0 = p_Pq + HID * HID;
    float* p_hs   = p_kvs0 + HID * HID;
    float* p_scal = p_hs + HID;
    const int ZSM = 5 * HID * HID + HID + 16;

    float* p_kvsF  = p_scal + 16;
    float* p_wqp   = p_kvsF + HID * HID;
    float* p_Wc    = p_wqp + HID * HID;
    float* p_kssum = p_Wc + HID * HID;
    float* p_kk    = p_kssum + HID;
    float* p_wvhs  = p_kk + HID;
    float* p_kq    = p_wvhs + HID;
    float* p_bqp   = p_kq + HID;
    float* p_bc    = p_bqp + HID;
    float* p_w1    = p_bc + HID;
    float* p_dinv  = p_w1 + HID;
    float* p_cs    = p_dinv + N_NODES;
    float* p_ct    = p_cs + NUM_GC * HID;
    float* p_cw    = p_ct + NUM_GC * HID;

    int* p_cnt     = ibase;
    int* p_off     = p_cnt + N_NODES;
    int* p_cur     = p_off + N_NODES + 1;
    int* p_csrc    = p_cur + N_NODES;
    int* p_partial = p_csrc + E_EDGES;
    int* p_pbase   = p_partial + 256;

    const dim3 gg(HID / 128, (N_NODES + 127) / 128);
    const dim3 gg2(HID / 128, (N_NODES + 127) / 128, 2);
    const int THR = 256;

    cudaFuncSetAttribute(sgemm128,
        cudaFuncAttributeMaxDynamicSharedMemorySize, TM_SMEM_BYTES);
    cudaFuncSetAttribute(sgemm128_b2,
        cudaFuncAttributeMaxDynamicSharedMemorySize, TM_SMEM_BYTES);
    cudaFuncSetAttribute(sgemm128_g2,
        cudaFuncAttributeMaxDynamicSharedMemorySize, TM_SMEM_BYTES);

    // ===== init + CSR build + coefficients =====
    bn_coef_kernel<<<(NUM_GC * HID + THR - 1) / THR, THR>>>(
        gcn_b0, gcn_b, bn_g, bn_b, bn_mean, bn_var, p_cs, p_ct);
    {
        int nmax = ZSM;
        if (G_GRP * HID > nmax) nmax = G_GRP * HID;
        if (N_NODES > nmax) nmax = N_NODES;
        init_kernel<<<(nmax + THR - 1) / THR, THR>>>(
            p_cnt, N_NODES, out_pool, G_GRP * HID, p_sm, ZSM);
    }
    count_kernel<<<(E_EDGES + THR - 1) / THR, THR>>>(dst, p_cnt);
    scan_partial_kernel<<<SCANBLK, THR>>>(p_cnt, p_partial);
    scan_base_kernel<<<1, THR>>>(p_partial, p_pbase);
    scan_fill_kernel<<<SCANBLK, THR>>>(p_cnt, p_pbase, p_off, p_cur, p_dinv);
    fill_kernel<<<(E_EDGES + THR - 1) / THR, THR>>>(src, dst, p_dinv, p_cur, p_csrc, p_cw);

    // ===== batched K=128 GEMMs: fc and gcn layer-0 (both A = x) =====
    sgemm128_b2<<<gg2, THR, TM_SMEM_BYTES>>>(x, fc_W, gcn_W0, fc_b, nullptr,
                                             p_t, p_gw, N_NODES, HID, F_IN);
    ln_relu_w<<<NROWBLK, THR>>>((const float4*)p_t, (const float4*)ln0_g,
                                (const float4*)ln0_b, (float4*)p_h);

    // ===== csr_agg layer 0 =====
    csr_agg_kernel<<<N_NODES / 4, THR>>>(
        (const float4*)p_gw, p_off, p_csrc, p_cw, p_dinv,
        p_cs, p_ct, (float4*)p_y);

    // ===== attention small-matrix algebra =====
    colsum_kernel<<<2048, THR>>>(p_h, p_hs);
    {
        const int SPLITS = 64;
        const int rows_per_z = (N_NODES + SPLITS - 1) / SPLITS;
        atb_sym_kernel<<<dim3(HID / 64, HID / 64, SPLITS), THR>>>(p_h, p_S, N_NODES, rows_per_z);
    }
    smalls1_kernel<<<HID + 3, THR>>>(p_S, Wk, Wv, Wq, p_hs, p_kk, p_wvhs, p_kq);
    atb3_kernel<<<dim3(4, 4, 3), THR>>>(p_S, Wv, Wk, Wq, p_U, p_Pk, p_Pq);
    atb1_kernel<<<dim3(4, 4), THR>>>(Wk, p_U, p_kvs0);
    trace2_kernel<<<2, THR>>>(p_Pk, Wk, bk, p_kk, p_Pq, Wq, bq, p_kq, p_scal);
    kvs_final_kernel<<<HID, THR>>>(p_kvs0, p_kk, p_wvhs, bk, bv, p_scal, p_kvsF, p_kssum);
    qprep_kernel<<<HID + 1 + HID / 8, THR>>>(Wq, p_kvsF, p_kssum, bq, p_wqp, p_bqp, p_w1);
    combine_kernel<<<HID + 1, THR>>>(p_wqp, Wv, p_bqp, bv, bq, p_kssum,
                                     p_scal, p_Wc, p_bc);

    // ===== batched independent GEMMs: t3 = H@Wc+bc AND GCN layer-1 =====
    sgemm128_g2<<<gg2, THR, TM_SMEM_BYTES>>>(p_h, p_Wc, p_bc, p_t,
                                             p_y, gcn_W, nullptr, p_gw,
                                             N_NODES, HID, HID);
    trans_epi_w<<<NROWBLK, THR>>>((const float4*)p_t, (const float4*)p_h,
                                  (const float4*)p_w1, p_scal,
                                  (const float4*)ln1_g, (const float4*)ln1_b,
                                  (float4*)out_xt);

    // ===== remaining GCN layers =====
    csr_agg_kernel<<<N_NODES / 4, THR>>>(
        (const float4*)p_gw, p_off, p_csrc, p_cw, p_dinv,
        p_cs + 1 * HID, p_ct + 1 * HID, (float4*)p_y);

    for (int i = 2; i < NUM_GC; i++) {
        const float* W = gcn_W + (size_t)(i - 1) * HID * HID;
        sgemm128<<<gg, THR, TM_SMEM_BYTES>>>(p_y, W, nullptr, p_gw, N_NODES, HID, HID);
        if (i < NUM_GC - 1) {
            csr_agg_kernel<<<N_NODES / 4, THR>>>(
                (const float4*)p_gw, p_off, p_csrc, p_cw, p_dinv,
                p_cs + (size_t)i * HID, p_ct + (size_t)i * HID, (float4*)p_y);
        } else {
            csr_agg_final<<<N_NODES / 4, THR>>>(
                (const float4*)p_gw, p_off, p_csrc, p_cw, p_dinv,
                p_cs + (size_t)(NUM_GC - 1) * HID, p_ct + (size_t)(NUM_GC - 1) * HID,
                batch, (float4*)out_g, out_pool);
        }
    }
}